// round 7
// baseline (speedup 1.0000x reference)
#include <cuda_runtime.h>
#include <math.h>
#include <mma.h>
using namespace nvcuda;

#define Bz   64
#define Lz   25
#define Fz   128
#define Pz   10000
#define Cz   400
#define BL   1600
#define PEPAD 10240
#define SLC  (Lz * Fz)          // 3200
#define WPAD 132                // padded row stride for W tile in smem (floats)
#define WQS  (32 * WPAD)        // 4224 floats (quarter W tile)

// ---------------- device scratch -------------------------------------------------
__device__ __align__(16) float g_st[10][BL * Fz];   // x, xc, out1..outc4
__device__ __align__(16) float g_v8[8][BL * Fz];    // v per call
__device__ float g_meanQ[8][4 * Bz * Lz];           // per call: [quarter][b][tau] raw sums
__device__ __align__(16) float g_pe[PEPAD * Fz];
__device__ unsigned g_maxbits = 0u;
__device__ unsigned g_minbits = 0x7F7FFFFFu;

// ================= K0: embed + minmax + padpe (mixed grid) ========================
__global__ void __launch_bounds__(256) k_pre(
        const int* __restrict__ user, const int* __restrict__ poi,
        const int* __restrict__ cat,  const int* __restrict__ tod,
        const int* __restrict__ dow,
        const float* __restrict__ ue,  const float* __restrict__ pe,
        const float* __restrict__ ce,  const float* __restrict__ te,
        const float* __restrict__ de,  const float* __restrict__ uec,
        const float* __restrict__ tec, const float* __restrict__ dec,
        const float* __restrict__ Dm) {
    const int bid = blockIdx.x, t = threadIdx.x;
    if (bid < 800) {
        int r = 2 * bid + (t >> 7);
        int d = t & 127;
        int u = user[r], p = poi[r], c = cat[r], td = tod[r], dw = dow[r];
        g_st[0][r * Fz + d] = ue[u * Fz + d]  + pe[p * Fz + d] + te[td * Fz + d]  + de[dw * Fz + d];
        g_st[1][r * Fz + d] = uec[u * Fz + d] + ce[c * Fz + d] + tec[td * Fz + d] + dec[dw * Fz + d];
    } else if (bid < 2400) {
        __shared__ float smx[256], smn[256];
        int row = poi[bid - 800];
        const float4* rp4 = (const float4*)(Dm + (size_t)row * Pz);
        float mx = -1e30f, mn = 1e30f;
        for (int p = t; p < Pz / 4; p += 256) {
            float4 v = __ldg(rp4 + p);
            mx = fmaxf(mx, fmaxf(fmaxf(v.x, v.y), fmaxf(v.z, v.w)));
            mn = fminf(mn, fminf(fminf(v.x, v.y), fminf(v.z, v.w)));
        }
        smx[t] = mx; smn[t] = mn; __syncthreads();
        for (int s = 128; s > 0; s >>= 1) {
            if (t < s) { smx[t] = fmaxf(smx[t], smx[t + s]); smn[t] = fminf(smn[t], smn[t + s]); }
            __syncthreads();
        }
        if (t == 0) {
            atomicMax(&g_maxbits, __float_as_uint(smx[0]));
            atomicMin(&g_minbits, __float_as_uint(smn[0]));
        }
    } else {
        int p0 = (bid - 2400) * 20;
        for (int it = 0; it < 10; it++) {
            int r = p0 + it * 2 + (t >> 7);
            int d = t & 127;
            float v = 0.f;
            if (r < Pz) v = wmma::__float_to_tf32(pe[r * Fz + d]);
            g_pe[r * Fz + d] = v;
        }
    }
}

// ======== stage 32x128 W quarter-tile into smem (coalesced), pad rows to 132 =====
__device__ __forceinline__ void stageW(float* __restrict__ Ws, const float* __restrict__ Wg,
                                       int quarter) {
    const int t = threadIdx.x;
    const float4* src = (const float4*)(Wg + (size_t)(quarter * 32) * Fz);
    #pragma unroll
    for (int i = t; i < 32 * 32; i += 512) {
        int row = i >> 5, c = i & 31;
        float4 w = __ldg(src + row * 32 + c);
        *(float4*)&Ws[row * WPAD + c * 4] = w;
    }
}

// ===== quarter-projection from smem W: dst[25][32] = in[25][128] @ Ws^T + b ======
// 512 threads: o = t&31, rg = t>>5 (0..15); rows rg and rg+16 (if rg<9)
__device__ __forceinline__ void projQ(float* __restrict__ dst, const float* __restrict__ in_full,
                                      const float* __restrict__ Ws, const float* __restrict__ bg,
                                      int quarter) {
    const int t = threadIdx.x;
    const int o = t & 31, rg = t >> 5;
    float a0 = 0.f, a1 = 0.f;
    const float4* W4 = (const float4*)(Ws + o * WPAD);
    const float4* A4 = (const float4*)in_full;
    #pragma unroll 8
    for (int c = 0; c < 32; c++) {
        float4 w = W4[c];
        float4 x = A4[rg * 32 + c];
        a0 += w.x * x.x + w.y * x.y + w.z * x.z + w.w * x.w;
        if (rg < 9) {
            x = A4[(rg + 16) * 32 + c];
            a1 += w.x * x.x + w.y * x.y + w.z * x.z + w.w * x.w;
        }
    }
    float bb = __ldg(bg + quarter * 32 + o);
    dst[rg * 32 + o] = a0 + bb;
    if (rg < 9) dst[(rg + 16) * 32 + o] = a1 + bb;
}

// ================= A op: qkv (quarter cols) + partial corr ========================
__device__ void doA(const float* __restrict__ inq, const float* __restrict__ inkv,
                    const float* __restrict__ Wc, const float* __restrict__ bc,
                    float* __restrict__ vdstG, float* __restrict__ meanQ,
                    float* __restrict__ qq, float* __restrict__ kq, float* __restrict__ vq,
                    float* __restrict__ Ws, int b, int quarter) {
    const int t = threadIdx.x;
    stageW(Ws, Wc, quarter);                     __syncthreads();
    projQ(qq, inq,  Ws, bc,          quarter);   __syncthreads();
    stageW(Ws, Wc + 1 * Fz * Fz, quarter);       __syncthreads();
    projQ(kq, inkv, Ws, bc + 1 * Fz, quarter);   __syncthreads();
    stageW(Ws, Wc + 2 * Fz * Fz, quarter);       __syncthreads();
    projQ(vq, inkv, Ws, bc + 2 * Fz, quarter);   __syncthreads();

    // store v quarter to global
    float* vd = vdstG + (size_t)b * SLC;
    for (int i = t; i < Lz * 32; i += 512) {
        int l = i >> 5, d = i & 31;
        vd[l * Fz + quarter * 32 + d] = vq[i];
    }
    // partial circular correlation over own 32 dims
    const float4* q4 = (const float4*)qq;
    const float4* k4 = (const float4*)kq;
    int w = t >> 5, lane = t & 31;
    for (int tau = w; tau < Lz; tau += 16) {
        float s = 0.f;
        for (int idx = lane; idx < Lz * 8; idx += 32) {
            int n = idx >> 3, d4 = idx & 7;
            int np = n + tau; if (np >= Lz) np -= Lz;
            float4 a = q4[np * 8 + d4];
            float4 bb = k4[idx];
            s += a.x * bb.x + a.y * bb.y + a.z * bb.z + a.w * bb.w;
        }
        #pragma unroll
        for (int off = 16; off > 0; off >>= 1) s += __shfl_down_sync(0xffffffffu, s, off);
        if (lane == 0) meanQ[quarter * Bz * Lz + b * Lz + tau] = s;
    }
}

// ================= A kernel (1 or 2 ops, 256 blocks each) =========================
__global__ void __launch_bounds__(512, 2) k_A(
        const float* q0, const float* kv0, const float* W0, const float* b0, float* v0, float* m0,
        const float* q1, const float* kv1, const float* W1, const float* b1, float* v1, float* m1) {
    extern __shared__ float sm[];
    float* inq  = sm;                       // 3200
    float* inkv = sm + SLC;                 // 3200
    float* qq   = sm + 2*SLC;               // 800
    float* kq   = sm + 2*SLC + 800;         // 800
    float* vq   = sm + 2*SLC + 1600;        // 800
    float* Ws   = sm + 2*SLC + 2400;        // 4224
    const int idx = blockIdx.x, t = threadIdx.x;
    const int op = idx >> 8, b = (idx >> 2) & 63, quarter = idx & 3;
    const float* qg  = op ? q1  : q0;
    const float* kvg = op ? kv1 : kv0;
    const float* Wc  = op ? W1  : W0;
    const float* bc  = op ? b1  : b0;
    float* vd = op ? v1 : v0;
    float* md = op ? m1 : m0;

    const float4* qs = (const float4*)(qg + (size_t)b * SLC);
    for (int i = t; i < SLC / 4; i += 512) ((float4*)inq)[i] = qs[i];
    const float* kbuf = inq;
    if (kvg != qg) {
        const float4* ks = (const float4*)(kvg + (size_t)b * SLC);
        for (int i = t; i < SLC / 4; i += 512) ((float4*)inkv)[i] = ks[i];
        kbuf = inkv;
    }
    __syncthreads();
    doA(inq, kbuf, Wc, bc, vd, md, qq, kq, vq, Ws, b, quarter);
}

// ================= B op: topk + softmax + agg + quarter out-proj ==================
__device__ void doB(const float* __restrict__ meanQ, const float* __restrict__ vsrc,
                    const float* __restrict__ Wp, const float* __restrict__ bp,
                    float* __restrict__ dstG,
                    float* __restrict__ ms, float* __restrict__ ag, float* __restrict__ outq,
                    float* __restrict__ Ws, int b, int quarter) {
    __shared__ float s_gms[Lz];
    __shared__ int   s_idx[3];
    __shared__ float s_tc[3];
    const int t = threadIdx.x;
    stageW(Ws, Wp, quarter);   // overlap with mean processing
    for (int i = t; i < Bz * Lz; i += 512)
        ms[i] = (meanQ[i] + meanQ[Bz * Lz + i] + meanQ[2 * Bz * Lz + i] + meanQ[3 * Bz * Lz + i]) * (1.0f / Fz);
    __syncthreads();
    if (t < Lz) {
        float s = 0.f;
        for (int bb = 0; bb < Bz; bb++) s += ms[bb * Lz + t];
        s_gms[t] = s;
    }
    __syncthreads();
    if (t == 0) {
        int id0 = 0, id1 = 0, id2 = 0;
        float v0 = -1e38f, v1 = -1e38f, v2 = -1e38f;
        for (int j = 0; j < Lz; j++) {
            float v = s_gms[j];
            if (v > v0)      { v2 = v1; id2 = id1; v1 = v0; id1 = id0; v0 = v; id0 = j; }
            else if (v > v1) { v2 = v1; id2 = id1; v1 = v; id1 = j; }
            else if (v > v2) { v2 = v; id2 = j; }
        }
        float w0 = ms[b * Lz + id0], w1 = ms[b * Lz + id1], w2 = ms[b * Lz + id2];
        float mx = fmaxf(w0, fmaxf(w1, w2));
        float e0 = expf(w0 - mx), e1 = expf(w1 - mx), e2 = expf(w2 - mx);
        float inv = 1.0f / (e0 + e1 + e2);
        s_tc[0] = e0 * inv; s_tc[1] = e1 * inv; s_tc[2] = e2 * inv;
        s_idx[0] = id0; s_idx[1] = id1; s_idx[2] = id2;
    }
    __syncthreads();
    {
        int i0 = s_idx[0], i1 = s_idx[1], i2 = s_idx[2];
        float c0 = s_tc[0], c1 = s_tc[1], c2 = s_tc[2];
        const float* vb = vsrc + (size_t)b * SLC;
        for (int i = t; i < SLC; i += 512) {
            int l = i >> 7, d = i & 127;
            int p0 = l + i0; if (p0 >= Lz) p0 -= Lz;
            int p1 = l + i1; if (p1 >= Lz) p1 -= Lz;
            int p2 = l + i2; if (p2 >= Lz) p2 -= Lz;
            ag[i] = c0 * vb[p0 * Fz + d] + c1 * vb[p1 * Fz + d] + c2 * vb[p2 * Fz + d];
        }
    }
    __syncthreads();
    projQ(outq, ag, Ws, bp, quarter);
    __syncthreads();
    float* dst = dstG + (size_t)b * SLC;
    for (int i = t; i < Lz * 32; i += 512) {
        int l = i >> 5, d = i & 31;
        dst[l * Fz + quarter * 32 + d] = outq[i];
    }
}

// ================= B kernel (1 or 2 ops, 256 blocks each) =========================
__global__ void __launch_bounds__(512, 2) k_B(
        const float* m0, const float* v0, const float* W0, const float* b0, float* d0,
        const float* m1, const float* v1, const float* W1, const float* b1, float* d1) {
    extern __shared__ float sm[];
    float* ms   = sm;                  // 1600
    float* ag   = sm + 1600;           // 3200
    float* outq = sm + 4800;           // 800
    float* Ws   = sm + 5600;           // 4224
    const int idx = blockIdx.x;
    const int op = idx >> 8, b = (idx >> 2) & 63, quarter = idx & 3;
    const float* mh = op ? m1 : m0;
    const float* vs = op ? v1 : v0;
    const float* Wp = op ? W1 : W0;
    const float* bp = op ? b1 : b0;
    float* dst = op ? d1 : d0;
    doB(mh, vs, Wp, bp, dst, ms, ag, outq, Ws, b, quarter);
}

// ================= final: POI (tf32 WMMA, fused exp-gather) + CAT =================
__global__ void __launch_bounds__(256) k_final(
        const float* __restrict__ outp, const float* __restrict__ outcp,
        const int* __restrict__ poi,  const float* __restrict__ Dm,
        const float* __restrict__ ce, const float* __restrict__ vw,
        const float* __restrict__ vbp, float* __restrict__ dst_poi,
        float* __restrict__ dst_cat) {
    extern __shared__ float sm[];
    const int bid = blockIdx.x, t = threadIdx.x;

    if (bid < 1280) {
        float* a_s = sm;
        float* S   = sm;
        __shared__ int   rows_s[50];
        __shared__ float vws[Lz];
        int wid = t >> 5;
        int ptile = bid % 40, b0 = (bid / 40) * 2;

        for (int i = t; i < 64 * 128; i += 256) {
            int r = i >> 7, d = i & 127;
            int l = r & 31, bb = b0 + (r >> 5);
            float v = 0.f;
            if (l < Lz) v = wmma::__float_to_tf32(outp[((bb * Lz) + l) * Fz + d]);
            a_s[i] = v;
        }
        if (t < 50) rows_s[t] = poi[(b0 + t / Lz) * Lz + (t % Lz)];
        if (t < Lz) vws[t] = vw[t];
        __syncthreads();

        wmma::fragment<wmma::matrix_a, 16, 16, 8, wmma::precision::tf32, wmma::row_major> fa;
        wmma::fragment<wmma::matrix_b, 16, 16, 8, wmma::precision::tf32, wmma::col_major> fb0, fb1;
        wmma::fragment<wmma::accumulator, 16, 16, 8, float> facc[4][2];
        #pragma unroll
        for (int m = 0; m < 4; m++) { wmma::fill_fragment(facc[m][0], 0.f); wmma::fill_fragment(facc[m][1], 0.f); }

        const float* peB = g_pe + (size_t)(ptile * 256) * Fz;
        for (int k = 0; k < 128; k += 8) {
            wmma::load_matrix_sync(fb0, peB + (size_t)((wid * 2 + 0) * 16) * Fz + k, Fz);
            wmma::load_matrix_sync(fb1, peB + (size_t)((wid * 2 + 1) * 16) * Fz + k, Fz);
            #pragma unroll
            for (int m = 0; m < 4; m++) {
                wmma::load_matrix_sync(fa, a_s + (m * 16) * Fz + k, Fz);
                wmma::mma_sync(facc[m][0], fa, fb0, facc[m][0]);
                wmma::mma_sync(facc[m][1], fa, fb1, facc[m][1]);
            }
        }
        __syncthreads();
        #pragma unroll
        for (int m = 0; m < 4; m++) {
            wmma::store_matrix_sync(S + (m * 16) * 264 + (wid * 2 + 0) * 16, facc[m][0], 264, wmma::mem_row_major);
            wmma::store_matrix_sync(S + (m * 16) * 264 + (wid * 2 + 1) * 16, facc[m][1], 264, wmma::mem_row_major);
        }
        __syncthreads();

        int p = ptile * 256 + t;
        if (p < Pz) {
            float neginv = -1.f / (__uint_as_float(g_maxbits) - __uint_as_float(g_minbits));
            float bias = vbp[0];
            #pragma unroll
            for (int bb = 0; bb < 2; bb++) {
                float r = 0.f;
                #pragma unroll
                for (int l = 0; l < Lz; l++) {
                    float s = S[(bb * 32 + l) * 264 + t];
                    float d = Dm[(size_t)rows_s[bb * Lz + l] * Pz + p];
                    r += s * __expf(d * neginv) * vws[l];
                }
                dst_poi[(size_t)(b0 + bb) * Pz + p] = r + bias;
            }
        }
    } else {
        int b = bid - 1280;
        float* y = sm;   // 128
        if (t < Fz) {
            float s = 0.f;
            for (int l = 0; l < Lz; l++) s += __ldg(&vw[l]) * outcp[(size_t)b * SLC + l * Fz + t];
            y[t] = s;
        }
        __syncthreads();
        int w = t >> 5, lane = t & 31;
        float bias = __ldg(vbp);
        const float4* Y4 = (const float4*)y;
        float4 yv = Y4[lane];
        for (int c = w; c < Cz; c += 8) {
            const float4* C4 = (const float4*)(ce + (size_t)c * Fz);
            float4 cv = __ldg(&C4[lane]);
            float s = cv.x * yv.x + cv.y * yv.y + cv.z * yv.z + cv.w * yv.w;
            #pragma unroll
            for (int off = 16; off > 0; off >>= 1) s += __shfl_down_sync(0xffffffffu, s, off);
            if (lane == 0) dst_cat[b * Cz + c] = s + bias;
        }
    }
}

// ---------------- host driver ----------------------------------------------------
extern "C" void kernel_launch(void* const* d_in, const int* in_sizes, int n_in,
                              void* d_out, int out_size) {
    const int*   user = (const int*)d_in[0];
    const int*   poi  = (const int*)d_in[1];
    const int*   cat  = (const int*)d_in[2];
    const int*   tod  = (const int*)d_in[5];
    const int*   dow  = (const int*)d_in[6];
    const float* ue   = (const float*)d_in[8];
    const float* pe   = (const float*)d_in[9];
    const float* ce   = (const float*)d_in[10];
    const float* te   = (const float*)d_in[11];
    const float* de   = (const float*)d_in[12];
    const float* uec  = (const float*)d_in[13];
    const float* tec  = (const float*)d_in[14];
    const float* dec  = (const float*)d_in[15];
    const float* W    = (const float*)d_in[16];
    const float* Bvv  = (const float*)d_in[17];
    const float* vw   = (const float*)d_in[18];
    const float* vb   = (const float*)d_in[19];
    const float* Dm   = (const float*)d_in[20];
    float* out = (float*)d_out;

    const int ASM = (2 * SLC + 3 * Lz * 32 + WQS) * 4;    // 52096 B
    const int BSM = (Bz * Lz + SLC + Lz * 32 + WQS) * 4;  // 39296 B
    const int FSM = 64 * 264 * 4;                          // 67584 B

    static int attr_done = 0;
    if (!attr_done) {
        cudaFuncSetAttribute(k_A,     cudaFuncAttributeMaxDynamicSharedMemorySize, ASM);
        cudaFuncSetAttribute(k_B,     cudaFuncAttributeMaxDynamicSharedMemorySize, BSM);
        cudaFuncSetAttribute(k_final, cudaFuncAttributeMaxDynamicSharedMemorySize, FSM);
        attr_done = 1;
    }

    float* stp;  cudaGetSymbolAddress((void**)&stp, g_st);
    float* vp;   cudaGetSymbolAddress((void**)&vp,  g_v8);
    float* mp;   cudaGetSymbolAddress((void**)&mp,  g_meanQ);
    #define ST(i)  (stp + (size_t)(i) * BL * Fz)
    #define VV(i)  (vp  + (size_t)(i) * BL * Fz)
    #define MM(i)  (mp  + (size_t)(i) * 4 * Bz * Lz)
    #define WQKV(c) (W   + (size_t)(c) * 4 * Fz * Fz)
    #define WPRJ(c) (W   + (size_t)(c) * 4 * Fz * Fz + 3 * Fz * Fz)
    #define BQKV(c) (Bvv + (size_t)(c) * 4 * Fz)
    #define BPRJ(c) (Bvv + (size_t)(c) * 4 * Fz + 3 * Fz)

    k_pre<<<2912, 256>>>(user, poi, cat, tod, dow, ue, pe, ce, te, de, uec, tec, dec, Dm);

    // c0: AC(x,x) ; c1: AC(xc,xc)
    k_A<<<512, 512, ASM>>>(ST(0), ST(0), WQKV(0), BQKV(0), VV(0), MM(0),
                           ST(1), ST(1), WQKV(1), BQKV(1), VV(1), MM(1));
    k_B<<<512, 512, BSM>>>(MM(0), VV(0), WPRJ(0), BPRJ(0), ST(2),
                           MM(1), VV(1), WPRJ(1), BPRJ(1), ST(3));
    // c2: AC(out1, outc1)
    k_A<<<256, 512, ASM>>>(ST(2), ST(3), WQKV(2), BQKV(2), VV(2), MM(2),
                           nullptr, nullptr, nullptr, nullptr, nullptr, nullptr);
    k_B<<<256, 512, BSM>>>(MM(2), VV(2), WPRJ(2), BPRJ(2), ST(4),
                           nullptr, nullptr, nullptr, nullptr, nullptr);
    // c3: AC(outc1, out2) ; c4 (=L2 c0): AC(out2, out2)
    k_A<<<512, 512, ASM>>>(ST(3), ST(4), WQKV(3), BQKV(3), VV(3), MM(3),
                           ST(4), ST(4), WQKV(4), BQKV(4), VV(4), MM(4));
    k_B<<<512, 512, BSM>>>(MM(3), VV(3), WPRJ(3), BPRJ(3), ST(5),
                           MM(4), VV(4), WPRJ(4), BPRJ(4), ST(6));
    // c5: AC(outc2, outc2)
    k_A<<<256, 512, ASM>>>(ST(5), ST(5), WQKV(5), BQKV(5), VV(5), MM(5),
                           nullptr, nullptr, nullptr, nullptr, nullptr, nullptr);
    k_B<<<256, 512, BSM>>>(MM(5), VV(5), WPRJ(5), BPRJ(5), ST(7),
                           nullptr, nullptr, nullptr, nullptr, nullptr);
    // c6: AC(out3, outc3)
    k_A<<<256, 512, ASM>>>(ST(6), ST(7), WQKV(6), BQKV(6), VV(6), MM(6),
                           nullptr, nullptr, nullptr, nullptr, nullptr, nullptr);
    k_B<<<256, 512, BSM>>>(MM(6), VV(6), WPRJ(6), BPRJ(6), ST(8),
                           nullptr, nullptr, nullptr, nullptr, nullptr);
    // c7: AC(outc3, out4)
    k_A<<<256, 512, ASM>>>(ST(7), ST(8), WQKV(7), BQKV(7), VV(7), MM(7),
                           nullptr, nullptr, nullptr, nullptr, nullptr, nullptr);
    k_B<<<256, 512, BSM>>>(MM(7), VV(7), WPRJ(7), BPRJ(7), ST(9),
                           nullptr, nullptr, nullptr, nullptr, nullptr);

    // final: POI (1280 blocks) + CAT (64 blocks)
    k_final<<<1344, 256, FSM>>>(ST(8), ST(9), poi, Dm, ce, vw, vb,
                                out, out + (size_t)Bz * Pz);
}

// round 8
// speedup vs baseline: 1.0997x; 1.0997x over previous
#include <cuda_runtime.h>
#include <math.h>
#include <mma.h>
using namespace nvcuda;

#define Bz   64
#define Lz   25
#define Fz   128
#define Pz   10000
#define Cz   400
#define BL   1600
#define PEPAD 10240
#define SLC  (Lz * Fz)          // 3200
#define WPAD 132                // padded row stride for W tile in smem (floats)
#define WHS  (64 * WPAD)        // 8448 floats (half W tile)

// ---------------- device scratch -------------------------------------------------
__device__ __align__(16) float g_st[10][BL * Fz];   // x, xc, out1..outc4
__device__ __align__(16) float g_v8[8][BL * Fz];    // v per call
__device__ float g_meanH[8][2 * Bz * Lz];           // per call: [half][b][tau] raw sums
__device__ __align__(16) float g_pe[PEPAD * Fz];
__device__ unsigned g_maxbits = 0u;
__device__ unsigned g_minbits = 0x7F7FFFFFu;

// ================= K0: embed + minmax + padpe (mixed grid) ========================
__global__ void __launch_bounds__(256) k_pre(
        const int* __restrict__ user, const int* __restrict__ poi,
        const int* __restrict__ cat,  const int* __restrict__ tod,
        const int* __restrict__ dow,
        const float* __restrict__ ue,  const float* __restrict__ pe,
        const float* __restrict__ ce,  const float* __restrict__ te,
        const float* __restrict__ de,  const float* __restrict__ uec,
        const float* __restrict__ tec, const float* __restrict__ dec,
        const float* __restrict__ Dm) {
    const int bid = blockIdx.x, t = threadIdx.x;
    if (bid < 800) {
        int r = 2 * bid + (t >> 7);
        int d = t & 127;
        int u = user[r], p = poi[r], c = cat[r], td = tod[r], dw = dow[r];
        g_st[0][r * Fz + d] = ue[u * Fz + d]  + pe[p * Fz + d] + te[td * Fz + d]  + de[dw * Fz + d];
        g_st[1][r * Fz + d] = uec[u * Fz + d] + ce[c * Fz + d] + tec[td * Fz + d] + dec[dw * Fz + d];
    } else if (bid < 4000) {
        // minmax over half of one gathered D row (2 blocks per row)
        __shared__ float smx[256], smn[256];
        int rid = bid - 800;
        int row = poi[rid >> 1];
        int part = rid & 1;
        const float4* rp4 = (const float4*)(Dm + (size_t)row * Pz);
        float mx = -1e30f, mn = 1e30f;
        for (int p = part * 1250 + t; p < (part + 1) * 1250; p += 256) {
            float4 v = __ldg(rp4 + p);
            mx = fmaxf(mx, fmaxf(fmaxf(v.x, v.y), fmaxf(v.z, v.w)));
            mn = fminf(mn, fminf(fminf(v.x, v.y), fminf(v.z, v.w)));
        }
        smx[t] = mx; smn[t] = mn; __syncthreads();
        for (int s = 128; s > 0; s >>= 1) {
            if (t < s) { smx[t] = fmaxf(smx[t], smx[t + s]); smn[t] = fminf(smn[t], smn[t + s]); }
            __syncthreads();
        }
        if (t == 0) {
            atomicMax(&g_maxbits, __float_as_uint(smx[0]));
            atomicMin(&g_minbits, __float_as_uint(smn[0]));
        }
    } else {
        int p0 = (bid - 4000) * 20;
        for (int it = 0; it < 10; it++) {
            int r = p0 + it * 2 + (t >> 7);
            int d = t & 127;
            float v = 0.f;
            if (r < Pz) v = wmma::__float_to_tf32(pe[r * Fz + d]);
            g_pe[r * Fz + d] = v;
        }
    }
}

// ======== stage 64x128 W half-tile into smem (coalesced), pad rows to 132 ========
__device__ __forceinline__ void stageW(float* __restrict__ Ws, const float* __restrict__ Wg,
                                       int half) {
    const int t = threadIdx.x;
    const float4* src = (const float4*)(Wg + (size_t)(half * 64) * Fz);
    #pragma unroll
    for (int i = t; i < 64 * 32; i += 256) {
        int row = i >> 5, c = i & 31;
        float4 w = __ldg(src + row * 32 + c);
        *(float4*)&Ws[row * WPAD + c * 4] = w;
    }
}

// ===== half-projection: dst[25][stride] = in[25][128] @ Ws^T + b ==================
// 256 threads: cp = t&31 -> output local cols cp and cp+32; rg = t>>5 (0..7)
//   rows rg, rg+8, rg+16, and 24 (rg==0 only). dst indexed dst[row*dstride + col].
__device__ __forceinline__ void projH2(float* __restrict__ dst, int dstride,
                                       const float* __restrict__ in_full,
                                       const float* __restrict__ Ws,
                                       const float* __restrict__ bg, int half) {
    const int t = threadIdx.x;
    const int cp = t & 31, rg = t >> 5;
    float a00 = 0.f, a01 = 0.f, a10 = 0.f, a11 = 0.f;
    float a20 = 0.f, a21 = 0.f, a30 = 0.f, a31 = 0.f;
    const float4* Wa = (const float4*)(Ws + cp * WPAD);
    const float4* Wb = (const float4*)(Ws + (cp + 32) * WPAD);
    const float4* A4 = (const float4*)in_full;
    #pragma unroll 4
    for (int c = 0; c < 32; c++) {
        float4 wa = Wa[c], wb = Wb[c];
        float4 x;
        x = A4[rg * 32 + c];
        a00 += wa.x * x.x + wa.y * x.y + wa.z * x.z + wa.w * x.w;
        a01 += wb.x * x.x + wb.y * x.y + wb.z * x.z + wb.w * x.w;
        x = A4[(rg + 8) * 32 + c];
        a10 += wa.x * x.x + wa.y * x.y + wa.z * x.z + wa.w * x.w;
        a11 += wb.x * x.x + wb.y * x.y + wb.z * x.z + wb.w * x.w;
        x = A4[(rg + 16) * 32 + c];
        a20 += wa.x * x.x + wa.y * x.y + wa.z * x.z + wa.w * x.w;
        a21 += wb.x * x.x + wb.y * x.y + wb.z * x.z + wb.w * x.w;
        if (rg == 0) {
            x = A4[24 * 32 + c];
            a30 += wa.x * x.x + wa.y * x.y + wa.z * x.z + wa.w * x.w;
            a31 += wb.x * x.x + wb.y * x.y + wb.z * x.z + wb.w * x.w;
        }
    }
    float b0 = __ldg(bg + half * 64 + cp);
    float b1 = __ldg(bg + half * 64 + cp + 32);
    dst[(rg     ) * dstride + cp     ] = a00 + b0;
    dst[(rg     ) * dstride + cp + 32] = a01 + b1;
    dst[(rg +  8) * dstride + cp     ] = a10 + b0;
    dst[(rg +  8) * dstride + cp + 32] = a11 + b1;
    dst[(rg + 16) * dstride + cp     ] = a20 + b0;
    dst[(rg + 16) * dstride + cp + 32] = a21 + b1;
    if (rg == 0) {
        dst[24 * dstride + cp     ] = a30 + b0;
        dst[24 * dstride + cp + 32] = a31 + b1;
    }
}

// ================= A kernel (1 or 2 ops, 128 blocks each) =========================
__global__ void __launch_bounds__(256, 2) k_A(
        const float* q0, const float* kv0, const float* W0, const float* b0, float* v0, float* m0,
        const float* q1, const float* kv1, const float* W1, const float* b1, float* v1, float* m1) {
    extern __shared__ float sm[];
    float* inq  = sm;              // 3200
    float* inkv = sm + 3200;       // 3200
    float* qq   = sm + 6400;       // 1600  [25][64]
    float* kq   = sm + 8000;       // 1600
    float* Ws   = sm + 9600;       // 8448
    const int idx = blockIdx.x, t = threadIdx.x;
    const int op = idx >> 7, b = (idx >> 1) & 63, half = idx & 1;
    const float* qg  = op ? q1  : q0;
    const float* kvg = op ? kv1 : kv0;
    const float* Wc  = op ? W1  : W0;
    const float* bc  = op ? b1  : b0;
    float* vd = op ? v1 : v0;
    float* md = op ? m1 : m0;

    const float4* qs = (const float4*)(qg + (size_t)b * SLC);
    for (int i = t; i < SLC / 4; i += 256) ((float4*)inq)[i] = qs[i];
    const float* kbuf = inq;
    if (kvg != qg) {
        const float4* ks = (const float4*)(kvg + (size_t)b * SLC);
        for (int i = t; i < SLC / 4; i += 256) ((float4*)inkv)[i] = ks[i];
        kbuf = inkv;
    }
    __syncthreads();

    stageW(Ws, Wc, half);                            __syncthreads();
    projH2(qq, 64, inq, Ws, bc, half);               __syncthreads();
    stageW(Ws, Wc + 1 * Fz * Fz, half);              __syncthreads();
    projH2(kq, 64, kbuf, Ws, bc + 1 * Fz, half);     __syncthreads();
    stageW(Ws, Wc + 2 * Fz * Fz, half);              __syncthreads();
    // v projection writes straight to global (coalesced scalar stores)
    projH2(vd + (size_t)b * SLC + half * 64, Fz, kbuf, Ws, bc + 2 * Fz, half);

    // partial circular correlation over own 64 dims
    const float4* q4 = (const float4*)qq;
    const float4* k4 = (const float4*)kq;
    int w = t >> 5, lane = t & 31;
    for (int tau = w; tau < Lz; tau += 8) {
        float s = 0.f;
        for (int i = lane; i < Lz * 16; i += 32) {
            int n = i >> 4, d4 = i & 15;
            int np = n + tau; if (np >= Lz) np -= Lz;
            float4 a = q4[np * 16 + d4];
            float4 bb = k4[i];
            s += a.x * bb.x + a.y * bb.y + a.z * bb.z + a.w * bb.w;
        }
        #pragma unroll
        for (int off = 16; off > 0; off >>= 1) s += __shfl_down_sync(0xffffffffu, s, off);
        if (lane == 0) md[half * Bz * Lz + b * Lz + tau] = s;
    }
}

// ================= B kernel (1 or 2 ops, 128 blocks each) =========================
__global__ void __launch_bounds__(256, 2) k_B(
        const float* m0, const float* v0, const float* W0, const float* b0, float* d0,
        const float* m1, const float* v1, const float* W1, const float* b1, float* d1) {
    extern __shared__ float sm[];
    float* ms = sm;            // 1600
    float* ag = sm + 1600;     // 3200
    float* Ws = sm + 4800;     // 8448
    __shared__ float s_gms[Lz];
    __shared__ int   s_idx[3];
    __shared__ float s_tc[3];
    const int idx = blockIdx.x, t = threadIdx.x;
    const int op = idx >> 7, b = (idx >> 1) & 63, half = idx & 1;
    const float* mh = op ? m1 : m0;
    const float* vs = op ? v1 : v0;
    const float* Wp = op ? W1 : W0;
    const float* bp = op ? b1 : b0;
    float* dst = op ? d1 : d0;

    stageW(Ws, Wp, half);          // overlaps with mean mirror
    for (int i = t; i < Bz * Lz; i += 256)
        ms[i] = (mh[i] + mh[Bz * Lz + i]) * (1.0f / Fz);
    __syncthreads();
    if (t < Lz) {
        float s = 0.f;
        for (int bb = 0; bb < Bz; bb++) s += ms[bb * Lz + t];
        s_gms[t] = s;
    }
    __syncthreads();
    if (t == 0) {
        int id0 = 0, id1 = 0, id2 = 0;
        float v0v = -1e38f, v1v = -1e38f, v2v = -1e38f;
        for (int j = 0; j < Lz; j++) {
            float v = s_gms[j];
            if (v > v0v)      { v2v = v1v; id2 = id1; v1v = v0v; id1 = id0; v0v = v; id0 = j; }
            else if (v > v1v) { v2v = v1v; id2 = id1; v1v = v; id1 = j; }
            else if (v > v2v) { v2v = v; id2 = j; }
        }
        float w0 = ms[b * Lz + id0], w1 = ms[b * Lz + id1], w2 = ms[b * Lz + id2];
        float mx = fmaxf(w0, fmaxf(w1, w2));
        float e0 = expf(w0 - mx), e1 = expf(w1 - mx), e2 = expf(w2 - mx);
        float inv = 1.0f / (e0 + e1 + e2);
        s_tc[0] = e0 * inv; s_tc[1] = e1 * inv; s_tc[2] = e2 * inv;
        s_idx[0] = id0; s_idx[1] = id1; s_idx[2] = id2;
    }
    __syncthreads();
    {
        int i0 = s_idx[0], i1 = s_idx[1], i2 = s_idx[2];
        float c0 = s_tc[0], c1 = s_tc[1], c2 = s_tc[2];
        const float4* vb4 = (const float4*)(vs + (size_t)b * SLC);
        float4* ag4 = (float4*)ag;
        for (int i = t; i < Lz * 32; i += 256) {
            int l = i >> 5, d4 = i & 31;
            int p0 = l + i0; if (p0 >= Lz) p0 -= Lz;
            int p1 = l + i1; if (p1 >= Lz) p1 -= Lz;
            int p2 = l + i2; if (p2 >= Lz) p2 -= Lz;
            float4 x0 = vb4[p0 * 32 + d4];
            float4 x1 = vb4[p1 * 32 + d4];
            float4 x2 = vb4[p2 * 32 + d4];
            float4 r;
            r.x = c0 * x0.x + c1 * x1.x + c2 * x2.x;
            r.y = c0 * x0.y + c1 * x1.y + c2 * x2.y;
            r.z = c0 * x0.z + c1 * x1.z + c2 * x2.z;
            r.w = c0 * x0.w + c1 * x1.w + c2 * x2.w;
            ag4[i] = r;
        }
    }
    __syncthreads();
    // output projection writes straight to global
    projH2(dst + (size_t)b * SLC + half * 64, Fz, ag, Ws, bp, half);
}

// ================= final: POI (tf32 WMMA, fused exp-gather) + CAT =================
__global__ void __launch_bounds__(256) k_final(
        const float* __restrict__ outp, const float* __restrict__ outcp,
        const int* __restrict__ poi,  const float* __restrict__ Dm,
        const float* __restrict__ ce, const float* __restrict__ vw,
        const float* __restrict__ vbp, float* __restrict__ dst_poi,
        float* __restrict__ dst_cat) {
    extern __shared__ float sm[];
    const int bid = blockIdx.x, t = threadIdx.x;

    if (bid < 1280) {
        float* a_s = sm;
        float* S   = sm;
        __shared__ int   rows_s[50];
        __shared__ float vws[Lz];
        int wid = t >> 5;
        int ptile = bid % 40, b0 = (bid / 40) * 2;

        for (int i = t; i < 64 * 128; i += 256) {
            int r = i >> 7, d = i & 127;
            int l = r & 31, bb = b0 + (r >> 5);
            float v = 0.f;
            if (l < Lz) v = wmma::__float_to_tf32(outp[((bb * Lz) + l) * Fz + d]);
            a_s[i] = v;
        }
        if (t < 50) rows_s[t] = poi[(b0 + t / Lz) * Lz + (t % Lz)];
        if (t < Lz) vws[t] = vw[t];
        __syncthreads();

        wmma::fragment<wmma::matrix_a, 16, 16, 8, wmma::precision::tf32, wmma::row_major> fa;
        wmma::fragment<wmma::matrix_b, 16, 16, 8, wmma::precision::tf32, wmma::col_major> fb0, fb1;
        wmma::fragment<wmma::accumulator, 16, 16, 8, float> facc[4][2];
        #pragma unroll
        for (int m = 0; m < 4; m++) { wmma::fill_fragment(facc[m][0], 0.f); wmma::fill_fragment(facc[m][1], 0.f); }

        const float* peB = g_pe + (size_t)(ptile * 256) * Fz;
        for (int k = 0; k < 128; k += 8) {
            wmma::load_matrix_sync(fb0, peB + (size_t)((wid * 2 + 0) * 16) * Fz + k, Fz);
            wmma::load_matrix_sync(fb1, peB + (size_t)((wid * 2 + 1) * 16) * Fz + k, Fz);
            #pragma unroll
            for (int m = 0; m < 4; m++) {
                wmma::load_matrix_sync(fa, a_s + (m * 16) * Fz + k, Fz);
                wmma::mma_sync(facc[m][0], fa, fb0, facc[m][0]);
                wmma::mma_sync(facc[m][1], fa, fb1, facc[m][1]);
            }
        }
        __syncthreads();
        #pragma unroll
        for (int m = 0; m < 4; m++) {
            wmma::store_matrix_sync(S + (m * 16) * 264 + (wid * 2 + 0) * 16, facc[m][0], 264, wmma::mem_row_major);
            wmma::store_matrix_sync(S + (m * 16) * 264 + (wid * 2 + 1) * 16, facc[m][1], 264, wmma::mem_row_major);
        }
        __syncthreads();

        int p = ptile * 256 + t;
        if (p < Pz) {
            float neginv = -1.f / (__uint_as_float(g_maxbits) - __uint_as_float(g_minbits));
            float bias = vbp[0];
            #pragma unroll
            for (int bb = 0; bb < 2; bb++) {
                float r = 0.f;
                #pragma unroll
                for (int l = 0; l < Lz; l++) {
                    float s = S[(bb * 32 + l) * 264 + t];
                    float d = Dm[(size_t)rows_s[bb * Lz + l] * Pz + p];
                    r += s * __expf(d * neginv) * vws[l];
                }
                dst_poi[(size_t)(b0 + bb) * Pz + p] = r + bias;
            }
        }
    } else {
        int b = bid - 1280;
        float* y = sm;   // 128
        if (t < Fz) {
            float s = 0.f;
            for (int l = 0; l < Lz; l++) s += __ldg(&vw[l]) * outcp[(size_t)b * SLC + l * Fz + t];
            y[t] = s;
        }
        __syncthreads();
        int w = t >> 5, lane = t & 31;
        float bias = __ldg(vbp);
        const float4* Y4 = (const float4*)y;
        float4 yv = Y4[lane];
        for (int c = w; c < Cz; c += 8) {
            const float4* C4 = (const float4*)(ce + (size_t)c * Fz);
            float4 cv = __ldg(&C4[lane]);
            float s = cv.x * yv.x + cv.y * yv.y + cv.z * yv.z + cv.w * yv.w;
            #pragma unroll
            for (int off = 16; off > 0; off >>= 1) s += __shfl_down_sync(0xffffffffu, s, off);
            if (lane == 0) dst_cat[b * Cz + c] = s + bias;
        }
    }
}

// ---------------- host driver ----------------------------------------------------
extern "C" void kernel_launch(void* const* d_in, const int* in_sizes, int n_in,
                              void* d_out, int out_size) {
    const int*   user = (const int*)d_in[0];
    const int*   poi  = (const int*)d_in[1];
    const int*   cat  = (const int*)d_in[2];
    const int*   tod  = (const int*)d_in[5];
    const int*   dow  = (const int*)d_in[6];
    const float* ue   = (const float*)d_in[8];
    const float* pe   = (const float*)d_in[9];
    const float* ce   = (const float*)d_in[10];
    const float* te   = (const float*)d_in[11];
    const float* de   = (const float*)d_in[12];
    const float* uec  = (const float*)d_in[13];
    const float* tec  = (const float*)d_in[14];
    const float* dec  = (const float*)d_in[15];
    const float* W    = (const float*)d_in[16];
    const float* Bvv  = (const float*)d_in[17];
    const float* vw   = (const float*)d_in[18];
    const float* vb   = (const float*)d_in[19];
    const float* Dm   = (const float*)d_in[20];
    float* out = (float*)d_out;

    const int ASM = (3200 + 3200 + 1600 + 1600 + WHS) * 4;   // 72192 B
    const int BSM = (1600 + 3200 + WHS) * 4;                  // 52992 B
    const int FSM = 64 * 264 * 4;                             // 67584 B

    static int attr_done = 0;
    if (!attr_done) {
        cudaFuncSetAttribute(k_A,     cudaFuncAttributeMaxDynamicSharedMemorySize, ASM);
        cudaFuncSetAttribute(k_B,     cudaFuncAttributeMaxDynamicSharedMemorySize, BSM);
        cudaFuncSetAttribute(k_final, cudaFuncAttributeMaxDynamicSharedMemorySize, FSM);
        attr_done = 1;
    }

    float* stp;  cudaGetSymbolAddress((void**)&stp, g_st);
    float* vp;   cudaGetSymbolAddress((void**)&vp,  g_v8);
    float* mp;   cudaGetSymbolAddress((void**)&mp,  g_meanH);
    #define ST(i)  (stp + (size_t)(i) * BL * Fz)
    #define VV(i)  (vp  + (size_t)(i) * BL * Fz)
    #define MM(i)  (mp  + (size_t)(i) * 2 * Bz * Lz)
    #define WQKV(c) (W   + (size_t)(c) * 4 * Fz * Fz)
    #define WPRJ(c) (W   + (size_t)(c) * 4 * Fz * Fz + 3 * Fz * Fz)
    #define BQKV(c) (Bvv + (size_t)(c) * 4 * Fz)
    #define BPRJ(c) (Bvv + (size_t)(c) * 4 * Fz + 3 * Fz)

    k_pre<<<4512, 256>>>(user, poi, cat, tod, dow, ue, pe, ce, te, de, uec, tec, dec, Dm);

    // c0: AC(x,x) ; c1: AC(xc,xc)
    k_A<<<256, 256, ASM>>>(ST(0), ST(0), WQKV(0), BQKV(0), VV(0), MM(0),
                           ST(1), ST(1), WQKV(1), BQKV(1), VV(1), MM(1));
    k_B<<<256, 256, BSM>>>(MM(0), VV(0), WPRJ(0), BPRJ(0), ST(2),
                           MM(1), VV(1), WPRJ(1), BPRJ(1), ST(3));
    // c2: AC(out1, outc1)
    k_A<<<128, 256, ASM>>>(ST(2), ST(3), WQKV(2), BQKV(2), VV(2), MM(2),
                           nullptr, nullptr, nullptr, nullptr, nullptr, nullptr);
    k_B<<<128, 256, BSM>>>(MM(2), VV(2), WPRJ(2), BPRJ(2), ST(4),
                           nullptr, nullptr, nullptr, nullptr, nullptr);
    // c3: AC(outc1, out2) ; c4 (=L2 c0): AC(out2, out2)
    k_A<<<256, 256, ASM>>>(ST(3), ST(4), WQKV(3), BQKV(3), VV(3), MM(3),
                           ST(4), ST(4), WQKV(4), BQKV(4), VV(4), MM(4));
    k_B<<<256, 256, BSM>>>(MM(3), VV(3), WPRJ(3), BPRJ(3), ST(5),
                           MM(4), VV(4), WPRJ(4), BPRJ(4), ST(6));
    // c5: AC(outc2, outc2)
    k_A<<<128, 256, ASM>>>(ST(5), ST(5), WQKV(5), BQKV(5), VV(5), MM(5),
                           nullptr, nullptr, nullptr, nullptr, nullptr, nullptr);
    k_B<<<128, 256, BSM>>>(MM(5), VV(5), WPRJ(5), BPRJ(5), ST(7),
                           nullptr, nullptr, nullptr, nullptr, nullptr);
    // c6: AC(out3, outc3)
    k_A<<<128, 256, ASM>>>(ST(6), ST(7), WQKV(6), BQKV(6), VV(6), MM(6),
                           nullptr, nullptr, nullptr, nullptr, nullptr, nullptr);
    k_B<<<128, 256, BSM>>>(MM(6), VV(6), WPRJ(6), BPRJ(6), ST(8),
                           nullptr, nullptr, nullptr, nullptr, nullptr);
    // c7: AC(outc3, out4)
    k_A<<<128, 256, ASM>>>(ST(7), ST(8), WQKV(7), BQKV(7), VV(7), MM(7),
                           nullptr, nullptr, nullptr, nullptr, nullptr, nullptr);
    k_B<<<128, 256, BSM>>>(MM(7), VV(7), WPRJ(7), BPRJ(7), ST(9),
                           nullptr, nullptr, nullptr, nullptr, nullptr);

    // final: POI (1280 blocks) + CAT (64 blocks)
    k_final<<<1344, 256, FSM>>>(ST(8), ST(9), poi, Dm, ce, vw, vb,
                                out, out + (size_t)Bz * Pz);
}

// round 9
// speedup vs baseline: 1.1353x; 1.0324x over previous
#include <cuda_runtime.h>
#include <cuda_pipeline.h>
#include <math.h>
#include <mma.h>
using namespace nvcuda;

#define Bz   64
#define Lz   25
#define Fz   128
#define Pz   10000
#define Cz   400
#define BL   1600
#define SLC  (Lz * Fz)          // 3200
#define WPAD 132                // padded row stride for W tile in smem (floats)
#define WHS  (64 * WPAD)        // 8448 floats (half W tile)

// ---------------- device scratch -------------------------------------------------
__device__ __align__(16) float g_st[10][BL * Fz];   // x, xc, out1..outc4
__device__ __align__(16) float g_v8[8][BL * Fz];    // v per call
__device__ __align__(16) float g_meanH[8][2 * Bz * Lz]; // per call: [half][b][tau]
__device__ __align__(16) float g_pe[10240 * Fz];
__device__ unsigned g_maxbits = 0u;
__device__ unsigned g_minbits = 0x7F7FFFFFu;

// ================= K0: embed + minmax + padpe (mixed grid) ========================
__global__ void __launch_bounds__(256) k_pre(
        const int* __restrict__ user, const int* __restrict__ poi,
        const int* __restrict__ cat,  const int* __restrict__ tod,
        const int* __restrict__ dow,
        const float* __restrict__ ue,  const float* __restrict__ pe,
        const float* __restrict__ ce,  const float* __restrict__ te,
        const float* __restrict__ de,  const float* __restrict__ uec,
        const float* __restrict__ tec, const float* __restrict__ dec,
        const float* __restrict__ Dm) {
    const int bid = blockIdx.x, t = threadIdx.x;
    if (bid < 800) {
        int r = 2 * bid + (t >> 7);
        int d = t & 127;
        int u = user[r], p = poi[r], c = cat[r], td = tod[r], dw = dow[r];
        g_st[0][r * Fz + d] = ue[u * Fz + d]  + pe[p * Fz + d] + te[td * Fz + d]  + de[dw * Fz + d];
        g_st[1][r * Fz + d] = uec[u * Fz + d] + ce[c * Fz + d] + tec[td * Fz + d] + dec[dw * Fz + d];
    } else if (bid < 4000) {
        __shared__ float smx[256], smn[256];
        int rid = bid - 800;
        int row = poi[rid >> 1];
        int part = rid & 1;
        const float4* rp4 = (const float4*)(Dm + (size_t)row * Pz);
        float mx = -1e30f, mn = 1e30f;
        for (int p = part * 1250 + t; p < (part + 1) * 1250; p += 256) {
            float4 v = __ldg(rp4 + p);
            mx = fmaxf(mx, fmaxf(fmaxf(v.x, v.y), fmaxf(v.z, v.w)));
            mn = fminf(mn, fminf(fminf(v.x, v.y), fminf(v.z, v.w)));
        }
        smx[t] = mx; smn[t] = mn; __syncthreads();
        for (int s = 128; s > 0; s >>= 1) {
            if (t < s) { smx[t] = fmaxf(smx[t], smx[t + s]); smn[t] = fminf(smn[t], smn[t + s]); }
            __syncthreads();
        }
        if (t == 0) {
            atomicMax(&g_maxbits, __float_as_uint(smx[0]));
            atomicMin(&g_minbits, __float_as_uint(smn[0]));
        }
    } else {
        int p0 = (bid - 4000) * 20;
        for (int it = 0; it < 10; it++) {
            int r = p0 + it * 2 + (t >> 7);
            int d = t & 127;
            float v = 0.f;
            if (r < Pz) v = wmma::__float_to_tf32(pe[r * Fz + d]);
            g_pe[r * Fz + d] = v;
        }
    }
}

// ======== async-stage 64x128 W half-tile into padded smem ========================
__device__ __forceinline__ void cpW(float* __restrict__ Ws, const float* __restrict__ Wg,
                                    int half) {
    const int t = threadIdx.x;
    const float4* src = (const float4*)(Wg + (size_t)(half * 64) * Fz);
    #pragma unroll
    for (int i = t; i < 64 * 32; i += 256) {
        int row = i >> 5, c = i & 31;
        __pipeline_memcpy_async(&Ws[row * WPAD + c * 4], &src[row * 32 + c], 16);
    }
}

// ===== half-projection: dst[25][stride] = in[25][128] @ Ws^T + b ==================
__device__ __forceinline__ void projH2(float* __restrict__ dst, int dstride,
                                       const float* __restrict__ in_full,
                                       const float* __restrict__ Ws,
                                       const float* __restrict__ bg, int half) {
    const int t = threadIdx.x;
    const int cp = t & 31, rg = t >> 5;
    float a00 = 0.f, a01 = 0.f, a10 = 0.f, a11 = 0.f;
    float a20 = 0.f, a21 = 0.f, a30 = 0.f, a31 = 0.f;
    const float4* Wa = (const float4*)(Ws + cp * WPAD);
    const float4* Wb = (const float4*)(Ws + (cp + 32) * WPAD);
    const float4* A4 = (const float4*)in_full;
    #pragma unroll 4
    for (int c = 0; c < 32; c++) {
        float4 wa = Wa[c], wb = Wb[c];
        float4 x;
        x = A4[rg * 32 + c];
        a00 += wa.x * x.x + wa.y * x.y + wa.z * x.z + wa.w * x.w;
        a01 += wb.x * x.x + wb.y * x.y + wb.z * x.z + wb.w * x.w;
        x = A4[(rg + 8) * 32 + c];
        a10 += wa.x * x.x + wa.y * x.y + wa.z * x.z + wa.w * x.w;
        a11 += wb.x * x.x + wb.y * x.y + wb.z * x.z + wb.w * x.w;
        x = A4[(rg + 16) * 32 + c];
        a20 += wa.x * x.x + wa.y * x.y + wa.z * x.z + wa.w * x.w;
        a21 += wb.x * x.x + wb.y * x.y + wb.z * x.z + wb.w * x.w;
        if (rg == 0) {
            x = A4[24 * 32 + c];
            a30 += wa.x * x.x + wa.y * x.y + wa.z * x.z + wa.w * x.w;
            a31 += wb.x * x.x + wb.y * x.y + wb.z * x.z + wb.w * x.w;
        }
    }
    float b0 = __ldg(bg + half * 64 + cp);
    float b1 = __ldg(bg + half * 64 + cp + 32);
    dst[(rg     ) * dstride + cp     ] = a00 + b0;
    dst[(rg     ) * dstride + cp + 32] = a01 + b1;
    dst[(rg +  8) * dstride + cp     ] = a10 + b0;
    dst[(rg +  8) * dstride + cp + 32] = a11 + b1;
    dst[(rg + 16) * dstride + cp     ] = a20 + b0;
    dst[(rg + 16) * dstride + cp + 32] = a21 + b1;
    if (rg == 0) {
        dst[24 * dstride + cp     ] = a30 + b0;
        dst[24 * dstride + cp + 32] = a31 + b1;
    }
}

// ================= A kernel: cp.async pipelined qkv + partial corr ================
__global__ void __launch_bounds__(256) k_A(
        const float* q0, const float* kv0, const float* W0, const float* b0, float* v0, float* m0,
        const float* q1, const float* kv1, const float* W1, const float* b1, float* v1, float* m1) {
    extern __shared__ float sm[];
    float* inq  = sm;              // 3200
    float* inkv = sm + 3200;       // 3200
    float* qq   = sm + 6400;       // 1600  [25][64]
    float* kq   = sm + 8000;       // 1600
    float* WsA  = sm + 9600;       // 8448
    float* WsB  = sm + 9600 + WHS; // 8448
    const int idx = blockIdx.x, t = threadIdx.x;
    const int op = idx >> 7, b = (idx >> 1) & 63, half = idx & 1;
    const float* qg  = op ? q1  : q0;
    const float* kvg = op ? kv1 : kv0;
    const float* Wc  = op ? W1  : W0;
    const float* bc  = op ? b1  : b0;
    float* vd = op ? v1 : v0;
    float* md = op ? m1 : m0;

    // --- issue all async copies up front ---
    const float4* qs = (const float4*)(qg + (size_t)b * SLC);
    for (int i = t; i < SLC / 4; i += 256)
        __pipeline_memcpy_async(&((float4*)inq)[i], &qs[i], 16);
    const float* kbuf = inq;
    if (kvg != qg) {
        const float4* ks = (const float4*)(kvg + (size_t)b * SLC);
        for (int i = t; i < SLC / 4; i += 256)
            __pipeline_memcpy_async(&((float4*)inkv)[i], &ks[i], 16);
        kbuf = inkv;
    }
    cpW(WsA, Wc, half);
    __pipeline_commit();                 // g0: inputs + Wq
    cpW(WsB, Wc + 1 * Fz * Fz, half);
    __pipeline_commit();                 // g1: Wk

    __pipeline_wait_prior(1);            // g0 done
    __syncthreads();
    projH2(qq, 64, inq, WsA, bc, half);
    __syncthreads();                     // all reads of WsA complete
    cpW(WsA, Wc + 2 * Fz * Fz, half);
    __pipeline_commit();                 // g2: Wv -> WsA
    __pipeline_wait_prior(1);            // g1 done
    __syncthreads();
    projH2(kq, 64, kbuf, WsB, bc + 1 * Fz, half);
    __pipeline_wait_prior(0);            // g2 done
    __syncthreads();                     // kq visible + Wv visible
    projH2(vd + (size_t)b * SLC + half * 64, Fz, kbuf, WsA, bc + 2 * Fz, half);

    // partial circular correlation over own 64 dims (qq/kq synced above)
    const float4* q4 = (const float4*)qq;
    const float4* k4 = (const float4*)kq;
    int w = t >> 5, lane = t & 31;
    for (int tau = w; tau < Lz; tau += 8) {
        float s = 0.f;
        for (int i = lane; i < Lz * 16; i += 32) {
            int n = i >> 4, d4 = i & 15;
            int np = n + tau; if (np >= Lz) np -= Lz;
            float4 a = q4[np * 16 + d4];
            float4 bb = k4[i];
            s += a.x * bb.x + a.y * bb.y + a.z * bb.z + a.w * bb.w;
        }
        #pragma unroll
        for (int off = 16; off > 0; off >>= 1) s += __shfl_down_sync(0xffffffffu, s, off);
        if (lane == 0) md[half * Bz * Lz + b * Lz + tau] = s;
    }
}

// ================= B kernel: prefetch v+W during topk, then agg + out-proj ========
__global__ void __launch_bounds__(256) k_B(
        const float* m0, const float* v0, const float* W0, const float* b0, float* d0,
        const float* m1, const float* v1, const float* W1, const float* b1, float* d1) {
    extern __shared__ float sm[];
    float* ms  = sm;               // 1600
    float* ag  = sm + 1600;        // 3200
    float* vss = sm + 4800;        // 3200
    float* Ws  = sm + 8000;        // 8448
    __shared__ float s_gms[Lz];
    __shared__ int   s_idx[3];
    __shared__ float s_tc[3];
    const int idx = blockIdx.x, t = threadIdx.x;
    const int op = idx >> 7, b = (idx >> 1) & 63, half = idx & 1;
    const float* mh = op ? m1 : m0;
    const float* vs = op ? v1 : v0;
    const float* Wp = op ? W1 : W0;
    const float* bp = op ? b1 : b0;
    float* dst = op ? d1 : d0;

    // async prefetch: full v slice + W half (overlap with mean/topk)
    {
        const float4* vb4 = (const float4*)(vs + (size_t)b * SLC);
        for (int i = t; i < SLC / 4; i += 256)
            __pipeline_memcpy_async(&((float4*)vss)[i], &vb4[i], 16);
        cpW(Ws, Wp, half);
        __pipeline_commit();
    }

    for (int i = t; i < Bz * Lz; i += 256)
        ms[i] = (mh[i] + mh[Bz * Lz + i]) * (1.0f / Fz);
    __syncthreads();
    if (t < Lz) {
        float s = 0.f;
        for (int bb = 0; bb < Bz; bb++) s += ms[bb * Lz + t];
        s_gms[t] = s;
    }
    __syncthreads();
    if (t == 0) {
        int id0 = 0, id1 = 0, id2 = 0;
        float v0v = -1e38f, v1v = -1e38f, v2v = -1e38f;
        for (int j = 0; j < Lz; j++) {
            float v = s_gms[j];
            if (v > v0v)      { v2v = v1v; id2 = id1; v1v = v0v; id1 = id0; v0v = v; id0 = j; }
            else if (v > v1v) { v2v = v1v; id2 = id1; v1v = v; id1 = j; }
            else if (v > v2v) { v2v = v; id2 = j; }
        }
        float w0 = ms[b * Lz + id0], w1 = ms[b * Lz + id1], w2 = ms[b * Lz + id2];
        float mx = fmaxf(w0, fmaxf(w1, w2));
        float e0 = expf(w0 - mx), e1 = expf(w1 - mx), e2 = expf(w2 - mx);
        float inv = 1.0f / (e0 + e1 + e2);
        s_tc[0] = e0 * inv; s_tc[1] = e1 * inv; s_tc[2] = e2 * inv;
        s_idx[0] = id0; s_idx[1] = id1; s_idx[2] = id2;
    }
    __pipeline_wait_prior(0);
    __syncthreads();     // topk results + v/W prefetch visible
    {
        int i0 = s_idx[0], i1 = s_idx[1], i2 = s_idx[2];
        float c0 = s_tc[0], c1 = s_tc[1], c2 = s_tc[2];
        const float4* vb4 = (const float4*)vss;
        float4* ag4 = (float4*)ag;
        for (int i = t; i < Lz * 32; i += 256) {
            int l = i >> 5, d4 = i & 31;
            int p0 = l + i0; if (p0 >= Lz) p0 -= Lz;
            int p1 = l + i1; if (p1 >= Lz) p1 -= Lz;
            int p2 = l + i2; if (p2 >= Lz) p2 -= Lz;
            float4 x0 = vb4[p0 * 32 + d4];
            float4 x1 = vb4[p1 * 32 + d4];
            float4 x2 = vb4[p2 * 32 + d4];
            float4 r;
            r.x = c0 * x0.x + c1 * x1.x + c2 * x2.x;
            r.y = c0 * x0.y + c1 * x1.y + c2 * x2.y;
            r.z = c0 * x0.z + c1 * x1.z + c2 * x2.z;
            r.w = c0 * x0.w + c1 * x1.w + c2 * x2.w;
            ag4[i] = r;
        }
    }
    __syncthreads();
    projH2(dst + (size_t)b * SLC + half * 64, Fz, ag, Ws, bp, half);
}

// ================= final: POI (tf32 WMMA, fused exp-gather) + CAT =================
__global__ void __launch_bounds__(256) k_final(
        const float* __restrict__ outp, const float* __restrict__ outcp,
        const int* __restrict__ poi,  const float* __restrict__ Dm,
        const float* __restrict__ ce, const float* __restrict__ vw,
        const float* __restrict__ vbp, float* __restrict__ dst_poi,
        float* __restrict__ dst_cat) {
    extern __shared__ float sm[];
    const int bid = blockIdx.x, t = threadIdx.x;

    if (bid < 1280) {
        float* a_s = sm;
        float* S   = sm;
        __shared__ int   rows_s[50];
        __shared__ float vws[Lz];
        int wid = t >> 5;
        int ptile = bid % 40, b0 = (bid / 40) * 2;

        for (int i = t; i < 64 * 128; i += 256) {
            int r = i >> 7, d = i & 127;
            int l = r & 31, bb = b0 + (r >> 5);
            float v = 0.f;
            if (l < Lz) v = wmma::__float_to_tf32(outp[((bb * Lz) + l) * Fz + d]);
            a_s[i] = v;
        }
        if (t < 50) rows_s[t] = poi[(b0 + t / Lz) * Lz + (t % Lz)];
        if (t < Lz) vws[t] = vw[t];
        __syncthreads();

        wmma::fragment<wmma::matrix_a, 16, 16, 8, wmma::precision::tf32, wmma::row_major> fa;
        wmma::fragment<wmma::matrix_b, 16, 16, 8, wmma::precision::tf32, wmma::col_major> fb0, fb1;
        wmma::fragment<wmma::accumulator, 16, 16, 8, float> facc[4][2];
        #pragma unroll
        for (int m = 0; m < 4; m++) { wmma::fill_fragment(facc[m][0], 0.f); wmma::fill_fragment(facc[m][1], 0.f); }

        const float* peB = g_pe + (size_t)(ptile * 256) * Fz;
        for (int k = 0; k < 128; k += 8) {
            wmma::load_matrix_sync(fb0, peB + (size_t)((wid * 2 + 0) * 16) * Fz + k, Fz);
            wmma::load_matrix_sync(fb1, peB + (size_t)((wid * 2 + 1) * 16) * Fz + k, Fz);
            #pragma unroll
            for (int m = 0; m < 4; m++) {
                wmma::load_matrix_sync(fa, a_s + (m * 16) * Fz + k, Fz);
                wmma::mma_sync(facc[m][0], fa, fb0, facc[m][0]);
                wmma::mma_sync(facc[m][1], fa, fb1, facc[m][1]);
            }
        }
        __syncthreads();
        #pragma unroll
        for (int m = 0; m < 4; m++) {
            wmma::store_matrix_sync(S + (m * 16) * 264 + (wid * 2 + 0) * 16, facc[m][0], 264, wmma::mem_row_major);
            wmma::store_matrix_sync(S + (m * 16) * 264 + (wid * 2 + 1) * 16, facc[m][1], 264, wmma::mem_row_major);
        }
        __syncthreads();

        int p = ptile * 256 + t;
        if (p < Pz) {
            float neginv = -1.f / (__uint_as_float(g_maxbits) - __uint_as_float(g_minbits));
            float bias = vbp[0];
            #pragma unroll
            for (int bb = 0; bb < 2; bb++) {
                float r = 0.f;
                #pragma unroll
                for (int l = 0; l < Lz; l++) {
                    float s = S[(bb * 32 + l) * 264 + t];
                    float d = Dm[(size_t)rows_s[bb * Lz + l] * Pz + p];
                    r += s * __expf(d * neginv) * vws[l];
                }
                dst_poi[(size_t)(b0 + bb) * Pz + p] = r + bias;
            }
        }
    } else {
        int b = bid - 1280;
        float* y = sm;   // 128
        if (t < Fz) {
            float s = 0.f;
            for (int l = 0; l < Lz; l++) s += __ldg(&vw[l]) * outcp[(size_t)b * SLC + l * Fz + t];
            y[t] = s;
        }
        __syncthreads();
        int w = t >> 5, lane = t & 31;
        float bias = __ldg(vbp);
        const float4* Y4 = (const float4*)y;
        float4 yv = Y4[lane];
        for (int c = w; c < Cz; c += 8) {
            const float4* C4 = (const float4*)(ce + (size_t)c * Fz);
            float4 cv = __ldg(&C4[lane]);
            float s = cv.x * yv.x + cv.y * yv.y + cv.z * yv.z + cv.w * yv.w;
            #pragma unroll
            for (int off = 16; off > 0; off >>= 1) s += __shfl_down_sync(0xffffffffu, s, off);
            if (lane == 0) dst_cat[b * Cz + c] = s + bias;
        }
    }
}

// ---------------- host driver ----------------------------------------------------
extern "C" void kernel_launch(void* const* d_in, const int* in_sizes, int n_in,
                              void* d_out, int out_size) {
    const int*   user = (const int*)d_in[0];
    const int*   poi  = (const int*)d_in[1];
    const int*   cat  = (const int*)d_in[2];
    const int*   tod  = (const int*)d_in[5];
    const int*   dow  = (const int*)d_in[6];
    const float* ue   = (const float*)d_in[8];
    const float* pe   = (const float*)d_in[9];
    const float* ce   = (const float*)d_in[10];
    const float* te   = (const float*)d_in[11];
    const float* de   = (const float*)d_in[12];
    const float* uec  = (const float*)d_in[13];
    const float* tec  = (const float*)d_in[14];
    const float* dec  = (const float*)d_in[15];
    const float* W    = (const float*)d_in[16];
    const float* Bvv  = (const float*)d_in[17];
    const float* vw   = (const float*)d_in[18];
    const float* vb   = (const float*)d_in[19];
    const float* Dm   = (const float*)d_in[20];
    float* out = (float*)d_out;

    const int ASM = (3200 + 3200 + 1600 + 1600 + 2 * WHS) * 4;  // 105984 B
    const int BSM = (1600 + 3200 + 3200 + WHS) * 4;             // 65792 B
    const int FSM = 64 * 264 * 4;                               // 67584 B

    static int attr_done = 0;
    if (!attr_done) {
        cudaFuncSetAttribute(k_A,     cudaFuncAttributeMaxDynamicSharedMemorySize, ASM);
        cudaFuncSetAttribute(k_B,     cudaFuncAttributeMaxDynamicSharedMemorySize, BSM);
        cudaFuncSetAttribute(k_final, cudaFuncAttributeMaxDynamicSharedMemorySize, FSM);
        attr_done = 1;
    }

    float* stp;  cudaGetSymbolAddress((void**)&stp, g_st);
    float* vp;   cudaGetSymbolAddress((void**)&vp,  g_v8);
    float* mp;   cudaGetSymbolAddress((void**)&mp,  g_meanH);
    #define ST(i)  (stp + (size_t)(i) * BL * Fz)
    #define VV(i)  (vp  + (size_t)(i) * BL * Fz)
    #define MM(i)  (mp  + (size_t)(i) * 2 * Bz * Lz)
    #define WQKV(c) (W   + (size_t)(c) * 4 * Fz * Fz)
    #define WPRJ(c) (W   + (size_t)(c) * 4 * Fz * Fz + 3 * Fz * Fz)
    #define BQKV(c) (Bvv + (size_t)(c) * 4 * Fz)
    #define BPRJ(c) (Bvv + (size_t)(c) * 4 * Fz + 3 * Fz)

    k_pre<<<4512, 256>>>(user, poi, cat, tod, dow, ue, pe, ce, te, de, uec, tec, dec, Dm);

    // c0: AC(x,x) ; c1: AC(xc,xc)
    k_A<<<256, 256, ASM>>>(ST(0), ST(0), WQKV(0), BQKV(0), VV(0), MM(0),
                           ST(1), ST(1), WQKV(1), BQKV(1), VV(1), MM(1));
    k_B<<<256, 256, BSM>>>(MM(0), VV(0), WPRJ(0), BPRJ(0), ST(2),
                           MM(1), VV(1), WPRJ(1), BPRJ(1), ST(3));
    // c2: AC(out1, outc1)
    k_A<<<128, 256, ASM>>>(ST(2), ST(3), WQKV(2), BQKV(2), VV(2), MM(2),
                           nullptr, nullptr, nullptr, nullptr, nullptr, nullptr);
    k_B<<<128, 256, BSM>>>(MM(2), VV(2), WPRJ(2), BPRJ(2), ST(4),
                           nullptr, nullptr, nullptr, nullptr, nullptr);
    // c3: AC(outc1, out2) ; c4 (=L2 c0): AC(out2, out2)
    k_A<<<256, 256, ASM>>>(ST(3), ST(4), WQKV(3), BQKV(3), VV(3), MM(3),
                           ST(4), ST(4), WQKV(4), BQKV(4), VV(4), MM(4));
    k_B<<<256, 256, BSM>>>(MM(3), VV(3), WPRJ(3), BPRJ(3), ST(5),
                           MM(4), VV(4), WPRJ(4), BPRJ(4), ST(6));
    // c5: AC(outc2, outc2)
    k_A<<<128, 256, ASM>>>(ST(5), ST(5), WQKV(5), BQKV(5), VV(5), MM(5),
                           nullptr, nullptr, nullptr, nullptr, nullptr, nullptr);
    k_B<<<128, 256, BSM>>>(MM(5), VV(5), WPRJ(5), BPRJ(5), ST(7),
                           nullptr, nullptr, nullptr, nullptr, nullptr);
    // c6: AC(out3, outc3)
    k_A<<<128, 256, ASM>>>(ST(6), ST(7), WQKV(6), BQKV(6), VV(6), MM(6),
                           nullptr, nullptr, nullptr, nullptr, nullptr, nullptr);
    k_B<<<128, 256, BSM>>>(MM(6), VV(6), WPRJ(6), BPRJ(6), ST(8),
                           nullptr, nullptr, nullptr, nullptr, nullptr);
    // c7: AC(outc3, out4)
    k_A<<<128, 256, ASM>>>(ST(7), ST(8), WQKV(7), BQKV(7), VV(7), MM(7),
                           nullptr, nullptr, nullptr, nullptr, nullptr, nullptr);
    k_B<<<128, 256, BSM>>>(MM(7), VV(7), WPRJ(7), BPRJ(7), ST(9),
                           nullptr, nullptr, nullptr, nullptr, nullptr);

    // final: POI (1280 blocks) + CAT (64 blocks)
    k_final<<<1344, 256, FSM>>>(ST(8), ST(9), poi, Dm, ce, vw, vb,
                                out, out + (size_t)Bz * Pz);
}